// round 2
// baseline (speedup 1.0000x reference)
#include <cuda_runtime.h>
#include <math.h>

#define NN   50000
#define EE   800000
#define ET   (EE + NN)      // 850000 edges incl. self loops
#define INC  128
#define HH   8
#define HIDC 16
#define H1C  128            // HH*HIDC
#define OC   40
#define SLOPE 0.2f
#define NEG_INF __int_as_float(0xff800000)

// ---------------- scratch (static device memory; no allocs allowed) ----------
__device__ float g_h1[NN * H1C];          // layer1 features after W1
__device__ float g_as1[NN * HH];
__device__ float g_ad1[NN * HH];
__device__ float g_m1[NN * HH];
__device__ float g_den1[NN * HH];
__device__ float g_e1[(size_t)ET * HH];   // per-edge logits -> exp
__device__ float g_agg1[NN * H1C];        // layer1 aggregate, then relu(x+b1) in-place
__device__ float g_h2[NN * OC];
__device__ float g_as2[NN];
__device__ float g_ad2[NN];
__device__ float g_m2[NN];
__device__ float g_den2[NN];
__device__ float g_e2[ET];
__device__ float g_agg2[NN * OC];
__device__ int   g_is64;

// ---------------- helpers ----------------------------------------------------
__device__ __forceinline__ void atomicMaxF(float* addr, float v) {
    if (v >= 0.0f) atomicMax((int*)addr, __float_as_int(v));
    else           atomicMin((unsigned int*)addr, __float_as_uint(v));
}

__device__ __forceinline__ void redAdd4(float* p, float a, float b, float c, float d) {
    asm volatile("red.global.add.v4.f32 [%0], {%1,%2,%3,%4};"
                 :: "l"(p), "f"(a), "f"(b), "f"(c), "f"(d) : "memory");
}

__device__ __forceinline__ void load_edge(int e, const void* ei, int& s, int& d) {
    if (e >= EE) { s = e - EE; d = s; return; }
    if (g_is64) {
        const long long* p = (const long long*)ei;
        s = (int)p[e]; d = (int)p[EE + e];
    } else {
        const int* p = (const int*)ei;
        s = p[e]; d = p[EE + e];
    }
}

// ---------------- kernels ----------------------------------------------------
__global__ void k_detect(const unsigned int* p) {
    unsigned int acc = 0;
    for (int i = 0; i < 64; i++) acc |= p[2 * i + 1];
    g_is64 = (acc == 0) ? 1 : 0;
}

__global__ void k_init() {
    int idx = blockIdx.x * blockDim.x + threadIdx.x;
    if (idx < NN * H1C) g_agg1[idx] = 0.0f;
    if (idx < NN * OC)  g_agg2[idx] = 0.0f;
    if (idx < NN * HH)  { g_m1[idx] = NEG_INF; g_den1[idx] = 0.0f; }
    if (idx < NN)       { g_m2[idx] = NEG_INF; g_den2[idx] = 0.0f; }
}

// h1 = x @ W1 (50000x128x128) + fused per-head attention halves
__global__ void k_gemm1(const float* __restrict__ X, const float* __restrict__ W,
                        const float* __restrict__ aS, const float* __restrict__ aD) {
    __shared__ float Xs[64][33];
    __shared__ float Ws[32][128];
    const int tid  = threadIdx.x;              // 256
    const int row0 = blockIdx.x * 64;
    const int lane = tid & 31;
    const int cx   = lane * 4;                 // 0..124
    const int ry   = (tid >> 5) * 8;           // 0..56

    float acc[8][4];
#pragma unroll
    for (int i = 0; i < 8; i++)
#pragma unroll
        for (int j = 0; j < 4; j++) acc[i][j] = 0.0f;

    for (int k0 = 0; k0 < 128; k0 += 32) {
#pragma unroll
        for (int i = 0; i < 8; i++) {
            int idx = tid + i * 256;
            int r = idx >> 5, c = idx & 31;
            int gr = row0 + r;
            Xs[r][c] = (gr < NN) ? X[gr * 128 + k0 + c] : 0.0f;
        }
#pragma unroll
        for (int i = 0; i < 16; i++) {
            int idx = tid + i * 256;
            int r = idx >> 7, c = idx & 127;
            Ws[r][c] = W[(k0 + r) * 128 + c];
        }
        __syncthreads();
#pragma unroll
        for (int kk = 0; kk < 32; kk++) {
            float4 wv = *(const float4*)&Ws[kk][cx];
#pragma unroll
            for (int i = 0; i < 8; i++) {
                float xv = Xs[ry + i][kk];
                acc[i][0] += xv * wv.x;
                acc[i][1] += xv * wv.y;
                acc[i][2] += xv * wv.z;
                acc[i][3] += xv * wv.w;
            }
        }
        __syncthreads();
    }

    float as0 = aS[cx], as1 = aS[cx+1], as2 = aS[cx+2], as3 = aS[cx+3];
    float ad0 = aD[cx], ad1 = aD[cx+1], ad2 = aD[cx+2], ad3 = aD[cx+3];

#pragma unroll
    for (int i = 0; i < 8; i++) {
        int gr = row0 + ry + i;
        bool ok = (gr < NN);
        if (ok) {
            float4 v = make_float4(acc[i][0], acc[i][1], acc[i][2], acc[i][3]);
            *(float4*)&g_h1[gr * 128 + cx] = v;
        }
        float ps = acc[i][0]*as0 + acc[i][1]*as1 + acc[i][2]*as2 + acc[i][3]*as3;
        float pd = acc[i][0]*ad0 + acc[i][1]*ad1 + acc[i][2]*ad2 + acc[i][3]*ad3;
        ps += __shfl_xor_sync(0xffffffff, ps, 1);
        ps += __shfl_xor_sync(0xffffffff, ps, 2);
        pd += __shfl_xor_sync(0xffffffff, pd, 1);
        pd += __shfl_xor_sync(0xffffffff, pd, 2);
        if (ok && (lane & 3) == 0) {
            int h = lane >> 2;
            g_as1[gr * HH + h] = ps;
            g_ad1[gr * HH + h] = pd;
        }
    }
}

__global__ void k_edge1_logit(const void* __restrict__ ei) {
    int e = blockIdx.x * blockDim.x + threadIdx.x;
    if (e >= ET) return;
    int s, d; load_edge(e, ei, s, d);
    float4 s0 = *(const float4*)&g_as1[s * 8];
    float4 s1 = *(const float4*)&g_as1[s * 8 + 4];
    float4 d0 = *(const float4*)&g_ad1[d * 8];
    float4 d1 = *(const float4*)&g_ad1[d * 8 + 4];
    float v[8] = { s0.x+d0.x, s0.y+d0.y, s0.z+d0.z, s0.w+d0.w,
                   s1.x+d1.x, s1.y+d1.y, s1.z+d1.z, s1.w+d1.w };
#pragma unroll
    for (int h = 0; h < 8; h++) {
        v[h] = (v[h] >= 0.0f) ? v[h] : SLOPE * v[h];
        atomicMaxF(&g_m1[d * 8 + h], v[h]);
    }
    size_t base = (size_t)e * 8;
    *(float4*)&g_e1[base]     = make_float4(v[0], v[1], v[2], v[3]);
    *(float4*)&g_e1[base + 4] = make_float4(v[4], v[5], v[6], v[7]);
}

__global__ void k_edge1_exp(const void* __restrict__ ei) {
    int e = blockIdx.x * blockDim.x + threadIdx.x;
    if (e >= ET) return;
    int s, d; load_edge(e, ei, s, d);
    size_t base = (size_t)e * 8;
    float4 v0 = *(const float4*)&g_e1[base];
    float4 v1 = *(const float4*)&g_e1[base + 4];
    float4 m0 = *(const float4*)&g_m1[d * 8];
    float4 m1 = *(const float4*)&g_m1[d * 8 + 4];
    v0.x = __expf(v0.x - m0.x); v0.y = __expf(v0.y - m0.y);
    v0.z = __expf(v0.z - m0.z); v0.w = __expf(v0.w - m0.w);
    v1.x = __expf(v1.x - m1.x); v1.y = __expf(v1.y - m1.y);
    v1.z = __expf(v1.z - m1.z); v1.w = __expf(v1.w - m1.w);
    *(float4*)&g_e1[base]     = v0;
    *(float4*)&g_e1[base + 4] = v1;
    redAdd4(&g_den1[d * 8],     v0.x, v0.y, v0.z, v0.w);
    redAdd4(&g_den1[d * 8 + 4], v1.x, v1.y, v1.z, v1.w);
}

// one warp per edge; scatter-add 128 floats with vector red
__global__ void k_agg1(const void* __restrict__ ei) {
    int gtid = blockIdx.x * blockDim.x + threadIdx.x;
    int e = gtid >> 5;
    if (e >= ET) return;
    int lane = gtid & 31;
    int s, d; load_edge(e, ei, s, d);
    int h = lane >> 2;                                  // (lane*4)/16
    float alpha = g_e1[(size_t)e * 8 + h] / g_den1[d * 8 + h];
    float4 hv = *(const float4*)&g_h1[s * 128 + lane * 4];
    redAdd4(&g_agg1[d * 128 + lane * 4],
            hv.x * alpha, hv.y * alpha, hv.z * alpha, hv.w * alpha);
}

__global__ void k_relu_bias(const float* __restrict__ b1) {
    int idx = blockIdx.x * blockDim.x + threadIdx.x;
    if (idx >= NN * H1C) return;
    float v = g_agg1[idx] + b1[idx & 127];
    g_agg1[idx] = v > 0.0f ? v : 0.0f;
}

// h2 = relu1 @ W2 (50000x128x40) + fused attention halves (single head)
__global__ void k_gemm2(const float* __restrict__ W,
                        const float* __restrict__ aS, const float* __restrict__ aD) {
    __shared__ float Xs[128][33];
    __shared__ float Ws[32][40];
    const int tid  = threadIdx.x;             // 256
    const int row0 = blockIdx.x * 128;
    const int lane = tid & 31;
    const int cx   = (tid & 7) * 5;           // 0..35
    const int ry   = (tid >> 3) * 4;          // 0..124

    float acc[4][5];
#pragma unroll
    for (int i = 0; i < 4; i++)
#pragma unroll
        for (int j = 0; j < 5; j++) acc[i][j] = 0.0f;

    for (int k0 = 0; k0 < 128; k0 += 32) {
#pragma unroll
        for (int i = 0; i < 16; i++) {
            int idx = tid + i * 256;
            int r = idx >> 5, c = idx & 31;
            int gr = row0 + r;
            Xs[r][c] = (gr < NN) ? g_agg1[gr * 128 + k0 + c] : 0.0f;
        }
#pragma unroll
        for (int i = 0; i < 5; i++) {
            int idx = tid + i * 256;
            int r = idx / 40, c = idx % 40;
            Ws[r][c] = W[(k0 + r) * 40 + c];
        }
        __syncthreads();
#pragma unroll
        for (int kk = 0; kk < 32; kk++) {
            float wv[5];
#pragma unroll
            for (int j = 0; j < 5; j++) wv[j] = Ws[kk][cx + j];
#pragma unroll
            for (int i = 0; i < 4; i++) {
                float xv = Xs[ry + i][kk];
#pragma unroll
                for (int j = 0; j < 5; j++) acc[i][j] += xv * wv[j];
            }
        }
        __syncthreads();
    }

    float asr[5], adr[5];
#pragma unroll
    for (int j = 0; j < 5; j++) { asr[j] = aS[cx + j]; adr[j] = aD[cx + j]; }

#pragma unroll
    for (int i = 0; i < 4; i++) {
        int gr = row0 + ry + i;
        bool ok = (gr < NN);
        if (ok) {
#pragma unroll
            for (int j = 0; j < 5; j++) g_h2[gr * OC + cx + j] = acc[i][j];
        }
        float ps = 0.0f, pd = 0.0f;
#pragma unroll
        for (int j = 0; j < 5; j++) { ps += acc[i][j] * asr[j]; pd += acc[i][j] * adr[j]; }
        ps += __shfl_xor_sync(0xffffffff, ps, 1);
        ps += __shfl_xor_sync(0xffffffff, ps, 2);
        ps += __shfl_xor_sync(0xffffffff, ps, 4);
        pd += __shfl_xor_sync(0xffffffff, pd, 1);
        pd += __shfl_xor_sync(0xffffffff, pd, 2);
        pd += __shfl_xor_sync(0xffffffff, pd, 4);
        if (ok && (lane & 7) == 0) { g_as2[gr] = ps; g_ad2[gr] = pd; }
    }
}

__global__ void k_edge2_logit(const void* __restrict__ ei) {
    int e = blockIdx.x * blockDim.x + threadIdx.x;
    if (e >= ET) return;
    int s, d; load_edge(e, ei, s, d);
    float v = g_as2[s] + g_ad2[d];
    v = (v >= 0.0f) ? v : SLOPE * v;
    g_e2[e] = v;
    atomicMaxF(&g_m2[d], v);
}

__global__ void k_edge2_exp(const void* __restrict__ ei) {
    int e = blockIdx.x * blockDim.x + threadIdx.x;
    if (e >= ET) return;
    int s, d; load_edge(e, ei, s, d);
    float ex = __expf(g_e2[e] - g_m2[d]);
    g_e2[e] = ex;
    atomicAdd(&g_den2[d], ex);
}

// one warp per edge; 40 floats as 10 vector reds over lanes 0..9
__global__ void k_agg2(const void* __restrict__ ei) {
    int gtid = blockIdx.x * blockDim.x + threadIdx.x;
    int e = gtid >> 5;
    if (e >= ET) return;
    int lane = gtid & 31;
    int s, d; load_edge(e, ei, s, d);
    if (lane >= 10) return;
    float alpha = g_e2[e] / g_den2[d];
    float4 hv = *(const float4*)&g_h2[s * OC + lane * 4];
    redAdd4(&g_agg2[d * OC + lane * 4],
            hv.x * alpha, hv.y * alpha, hv.z * alpha, hv.w * alpha);
}

// one warp per node: out = log_softmax(agg2 + b2)
__global__ void k_final(const float* __restrict__ b2, float* __restrict__ out) {
    int gtid = blockIdx.x * blockDim.x + threadIdx.x;
    int n = gtid >> 5;
    if (n >= NN) return;
    int lane = gtid & 31;
    float v0 = g_agg2[n * OC + lane] + b2[lane];
    float v1 = (lane < 8) ? (g_agg2[n * OC + 32 + lane] + b2[32 + lane]) : NEG_INF;
    float m = fmaxf(v0, v1);
#pragma unroll
    for (int o = 16; o > 0; o >>= 1) m = fmaxf(m, __shfl_xor_sync(0xffffffff, m, o));
    float sum = __expf(v0 - m) + ((lane < 8) ? __expf(v1 - m) : 0.0f);
#pragma unroll
    for (int o = 16; o > 0; o >>= 1) sum += __shfl_xor_sync(0xffffffff, sum, o);
    float l = m + logf(sum);
    out[n * OC + lane] = v0 - l;
    if (lane < 8) out[n * OC + 32 + lane] = v1 - l;
}

// ---------------- launch -----------------------------------------------------
extern "C" void kernel_launch(void* const* d_in, const int* in_sizes, int n_in,
                              void* d_out, int out_size) {
    const float* x      = (const float*)d_in[0];
    const void*  ei     = d_in[1];
    const float* W1     = (const float*)d_in[2];
    const float* a1_src = (const float*)d_in[3];
    const float* a1_dst = (const float*)d_in[4];
    const float* b1     = (const float*)d_in[5];
    const float* W2     = (const float*)d_in[6];
    const float* a2_src = (const float*)d_in[7];
    const float* a2_dst = (const float*)d_in[8];
    const float* b2     = (const float*)d_in[9];
    float* out = (float*)d_out;

    k_detect<<<1, 1>>>((const unsigned int*)ei);
    k_init<<<(NN * H1C + 255) / 256, 256>>>();
    k_gemm1<<<(NN + 63) / 64, 256>>>(x, W1, a1_src, a1_dst);
    k_edge1_logit<<<(ET + 255) / 256, 256>>>(ei);
    k_edge1_exp<<<(ET + 255) / 256, 256>>>(ei);
    k_agg1<<<(ET * 32 + 255) / 256, 256>>>(ei);
    k_relu_bias<<<(NN * H1C + 255) / 256, 256>>>(b1);
    k_gemm2<<<(NN + 127) / 128, 256>>>(W2, a2_src, a2_dst);
    k_edge2_logit<<<(ET + 255) / 256, 256>>>(ei);
    k_edge2_exp<<<(ET + 255) / 256, 256>>>(ei);
    k_agg2<<<(ET * 32 + 255) / 256, 256>>>(ei);
    k_final<<<(NN * 32 + 255) / 256, 256>>>(b2, out);
}

// round 3
// speedup vs baseline: 1.7869x; 1.7869x over previous
#include <cuda_runtime.h>
#include <math.h>

#define NN   50000
#define EE   800000
#define HH   8
#define H1C  128
#define OC   40
#define SLOPE 0.2f
#define NEG_INF __int_as_float(0xff800000)

// ---------------- scratch -----------------------------------------------------
__device__ float g_h1[NN * H1C];
__device__ float g_as1[NN * HH];
__device__ float g_ad1[NN * HH];
__device__ float g_agg1[NN * H1C];     // relu(num/den + b1)
__device__ float g_h2[NN * OC];
__device__ float g_as2[NN];
__device__ float g_ad2[NN];
__device__ int   g_deg[NN];
__device__ int   g_off[NN];
__device__ int   g_cur[NN];
__device__ int   g_list[EE];           // src ids grouped by dst
__device__ int   g_is64;

// ---------------- helpers -----------------------------------------------------
__device__ __forceinline__ void load_edge(int e, const void* ei, int& s, int& d) {
    if (g_is64) {
        const long long* p = (const long long*)ei;
        s = (int)p[e]; d = (int)p[EE + e];
    } else {
        const int* p = (const int*)ei;
        s = p[e]; d = p[EE + e];
    }
}
__device__ __forceinline__ float leaky(float v) {
    return (v >= 0.0f) ? v : SLOPE * v;
}

// ---------------- CSR build ----------------------------------------------------
__global__ void k_detect(const unsigned int* p) {
    unsigned int acc = 0;
    for (int i = 0; i < 64; i++) acc |= p[2 * i + 1];
    g_is64 = (acc == 0) ? 1 : 0;
}

__global__ void k_zero() {
    int i = blockIdx.x * blockDim.x + threadIdx.x;
    if (i < NN) g_deg[i] = 0;
}

__global__ void k_count(const void* __restrict__ ei) {
    int e = blockIdx.x * blockDim.x + threadIdx.x;
    if (e >= EE) return;
    int s, d; load_edge(e, ei, s, d);
    atomicAdd(&g_deg[d], 1);
}

__global__ void k_scan() {                     // 1 block x 1024
    __shared__ int warpsum[32];
    __shared__ int carry_s;
    int tid = threadIdx.x;
    if (tid == 0) carry_s = 0;
    __syncthreads();
    for (int base = 0; base < NN; base += 1024) {
        int i = base + tid;
        int v = (i < NN) ? g_deg[i] : 0;
        int x = v;
#pragma unroll
        for (int o = 1; o < 32; o <<= 1) {
            int y = __shfl_up_sync(0xffffffff, x, o);
            if ((tid & 31) >= o) x += y;
        }
        if ((tid & 31) == 31) warpsum[tid >> 5] = x;
        __syncthreads();
        if (tid < 32) {
            int w = warpsum[tid];
#pragma unroll
            for (int o = 1; o < 32; o <<= 1) {
                int y = __shfl_up_sync(0xffffffff, w, o);
                if (tid >= o) w += y;
            }
            warpsum[tid] = w;
        }
        __syncthreads();
        int blockoff = (tid >= 32) ? warpsum[(tid >> 5) - 1] : 0;
        int excl = carry_s + blockoff + x - v;
        if (i < NN) { g_off[i] = excl; g_cur[i] = excl; }
        __syncthreads();
        if (tid == 1023) carry_s += blockoff + x;
        __syncthreads();
    }
}

__global__ void k_fill(const void* __restrict__ ei) {
    int e = blockIdx.x * blockDim.x + threadIdx.x;
    if (e >= EE) return;
    int s, d; load_edge(e, ei, s, d);
    int pos = atomicAdd(&g_cur[d], 1);
    g_list[pos] = s;
}

// ---------------- GEMM1: h1 = x @ W1, fused attention halves ------------------
__global__ void k_gemm1(const float* __restrict__ X, const float* __restrict__ W,
                        const float* __restrict__ aS, const float* __restrict__ aD) {
    __shared__ float Xs[64][33];
    __shared__ float Ws[32][128];
    const int tid  = threadIdx.x;              // 256
    const int row0 = blockIdx.x * 64;
    const int lane = tid & 31;
    const int cx   = lane * 4;
    const int ry   = (tid >> 5) * 8;

    float acc[8][4];
#pragma unroll
    for (int i = 0; i < 8; i++)
#pragma unroll
        for (int j = 0; j < 4; j++) acc[i][j] = 0.0f;

    for (int k0 = 0; k0 < 128; k0 += 32) {
#pragma unroll
        for (int i = 0; i < 8; i++) {
            int idx = tid + i * 256;
            int r = idx >> 5, c = idx & 31;
            int gr = row0 + r;
            Xs[r][c] = (gr < NN) ? X[gr * 128 + k0 + c] : 0.0f;
        }
#pragma unroll
        for (int i = 0; i < 16; i++) {
            int idx = tid + i * 256;
            int r = idx >> 7, c = idx & 127;
            Ws[r][c] = W[(k0 + r) * 128 + c];
        }
        __syncthreads();
#pragma unroll
        for (int kk = 0; kk < 32; kk++) {
            float4 wv = *(const float4*)&Ws[kk][cx];
#pragma unroll
            for (int i = 0; i < 8; i++) {
                float xv = Xs[ry + i][kk];
                acc[i][0] += xv * wv.x;
                acc[i][1] += xv * wv.y;
                acc[i][2] += xv * wv.z;
                acc[i][3] += xv * wv.w;
            }
        }
        __syncthreads();
    }

    float as0 = aS[cx], as1 = aS[cx+1], as2 = aS[cx+2], as3 = aS[cx+3];
    float ad0 = aD[cx], ad1 = aD[cx+1], ad2 = aD[cx+2], ad3 = aD[cx+3];

#pragma unroll
    for (int i = 0; i < 8; i++) {
        int gr = row0 + ry + i;
        bool ok = (gr < NN);
        if (ok) {
            float4 v = make_float4(acc[i][0], acc[i][1], acc[i][2], acc[i][3]);
            *(float4*)&g_h1[gr * 128 + cx] = v;
        }
        float ps = acc[i][0]*as0 + acc[i][1]*as1 + acc[i][2]*as2 + acc[i][3]*as3;
        float pd = acc[i][0]*ad0 + acc[i][1]*ad1 + acc[i][2]*ad2 + acc[i][3]*ad3;
        ps += __shfl_xor_sync(0xffffffff, ps, 1);
        ps += __shfl_xor_sync(0xffffffff, ps, 2);
        pd += __shfl_xor_sync(0xffffffff, pd, 1);
        pd += __shfl_xor_sync(0xffffffff, pd, 2);
        if (ok && (lane & 3) == 0) {
            int h = lane >> 2;
            g_as1[gr * HH + h] = ps;
            g_ad1[gr * HH + h] = pd;
        }
    }
}

// ---------------- layer1 aggregation: one warp per node -----------------------
// out[d] = relu( (exS·h1[d] + Σ_s ex(s)·h1[s]) / den + b1 )
__global__ void k_node_agg1(const float* __restrict__ b1) {
    int gtid = blockIdx.x * blockDim.x + threadIdx.x;
    int n = gtid >> 5;
    if (n >= NN) return;
    int lane = gtid & 31;
    int my_h = lane >> 2;            // head for this lane's 4 channels

    // per-head state lives in lanes 0..7
    float ad = 0.0f, as_self = 0.0f;
    if (lane < 8) {
        ad      = g_ad1[n * 8 + lane];
        as_self = g_as1[n * 8 + lane];
    }
    float ex = (lane < 8) ? __expf(leaky(as_self + ad)) : 0.0f;
    float den = ex;                   // self loop
    float exb = __shfl_sync(0xffffffff, ex, my_h);
    float4 hv = *(const float4*)&g_h1[n * 128 + lane * 4];
    float4 acc = make_float4(exb * hv.x, exb * hv.y, exb * hv.z, exb * hv.w);

    int beg = g_off[n];
    int end = beg + g_deg[n];
    for (int i = beg; i < end; i++) {
        int s = g_list[i];
        float e = 0.0f;
        if (lane < 8) e = __expf(leaky(g_as1[s * 8 + lane] + ad));
        den += e;
        float eb = __shfl_sync(0xffffffff, e, my_h);
        float4 h = *(const float4*)&g_h1[s * 128 + lane * 4];
        acc.x += eb * h.x; acc.y += eb * h.y;
        acc.z += eb * h.z; acc.w += eb * h.w;
    }
    float denb = __shfl_sync(0xffffffff, den, my_h);
    float inv = 1.0f / denb;
    float4 bv = *(const float4*)&b1[lane * 4];
    float4 o;
    o.x = fmaxf(acc.x * inv + bv.x, 0.0f);
    o.y = fmaxf(acc.y * inv + bv.y, 0.0f);
    o.z = fmaxf(acc.z * inv + bv.z, 0.0f);
    o.w = fmaxf(acc.w * inv + bv.w, 0.0f);
    *(float4*)&g_agg1[n * 128 + lane * 4] = o;
}

// ---------------- GEMM2: h2 = agg1 @ W2, fused attention halves ---------------
__global__ void k_gemm2(const float* __restrict__ W,
                        const float* __restrict__ aS, const float* __restrict__ aD) {
    __shared__ float Xs[128][33];
    __shared__ float Ws[32][40];
    const int tid  = threadIdx.x;             // 256
    const int row0 = blockIdx.x * 128;
    const int lane = tid & 31;
    const int cx   = (tid & 7) * 5;
    const int ry   = (tid >> 3) * 4;

    float acc[4][5];
#pragma unroll
    for (int i = 0; i < 4; i++)
#pragma unroll
        for (int j = 0; j < 5; j++) acc[i][j] = 0.0f;

    for (int k0 = 0; k0 < 128; k0 += 32) {
#pragma unroll
        for (int i = 0; i < 16; i++) {
            int idx = tid + i * 256;
            int r = idx >> 5, c = idx & 31;
            int gr = row0 + r;
            Xs[r][c] = (gr < NN) ? g_agg1[gr * 128 + k0 + c] : 0.0f;
        }
#pragma unroll
        for (int i = 0; i < 5; i++) {
            int idx = tid + i * 256;
            int r = idx / 40, c = idx % 40;
            Ws[r][c] = W[(k0 + r) * 40 + c];
        }
        __syncthreads();
#pragma unroll
        for (int kk = 0; kk < 32; kk++) {
            float wv[5];
#pragma unroll
            for (int j = 0; j < 5; j++) wv[j] = Ws[kk][cx + j];
#pragma unroll
            for (int i = 0; i < 4; i++) {
                float xv = Xs[ry + i][kk];
#pragma unroll
                for (int j = 0; j < 5; j++) acc[i][j] += xv * wv[j];
            }
        }
        __syncthreads();
    }

    float asr[5], adr[5];
#pragma unroll
    for (int j = 0; j < 5; j++) { asr[j] = aS[cx + j]; adr[j] = aD[cx + j]; }

#pragma unroll
    for (int i = 0; i < 4; i++) {
        int gr = row0 + ry + i;
        bool ok = (gr < NN);
        if (ok) {
#pragma unroll
            for (int j = 0; j < 5; j++) g_h2[gr * OC + cx + j] = acc[i][j];
        }
        float ps = 0.0f, pd = 0.0f;
#pragma unroll
        for (int j = 0; j < 5; j++) { ps += acc[i][j] * asr[j]; pd += acc[i][j] * adr[j]; }
        ps += __shfl_xor_sync(0xffffffff, ps, 1);
        ps += __shfl_xor_sync(0xffffffff, ps, 2);
        ps += __shfl_xor_sync(0xffffffff, ps, 4);
        pd += __shfl_xor_sync(0xffffffff, pd, 1);
        pd += __shfl_xor_sync(0xffffffff, pd, 2);
        pd += __shfl_xor_sync(0xffffffff, pd, 4);
        if (ok && (lane & 7) == 0) { g_as2[gr] = ps; g_ad2[gr] = pd; }
    }
}

// ---------------- layer2 aggregation + log_softmax: one warp per node ---------
__global__ void k_node_agg2(const float* __restrict__ b2, float* __restrict__ out) {
    int gtid = blockIdx.x * blockDim.x + threadIdx.x;
    int n = gtid >> 5;
    if (n >= NN) return;
    int lane = gtid & 31;

    float ad = g_ad2[n];                      // broadcast load
    float ex = __expf(leaky(g_as2[n] + ad));  // self loop (all lanes identical)
    float den = ex;
    float4 acc = make_float4(0.f, 0.f, 0.f, 0.f);
    if (lane < 10) {
        float4 h = *(const float4*)&g_h2[n * OC + lane * 4];
        acc.x = ex * h.x; acc.y = ex * h.y; acc.z = ex * h.z; acc.w = ex * h.w;
    }

    int beg = g_off[n];
    int end = beg + g_deg[n];
    for (int i = beg; i < end; i++) {
        int s = g_list[i];
        float e = __expf(leaky(g_as2[s] + ad));
        den += e;
        if (lane < 10) {
            float4 h = *(const float4*)&g_h2[s * OC + lane * 4];
            acc.x += e * h.x; acc.y += e * h.y;
            acc.z += e * h.z; acc.w += e * h.w;
        }
    }

    float inv = 1.0f / den;
    float4 v = make_float4(NEG_INF, NEG_INF, NEG_INF, NEG_INF);
    if (lane < 10) {
        v.x = acc.x * inv + b2[lane * 4];
        v.y = acc.y * inv + b2[lane * 4 + 1];
        v.z = acc.z * inv + b2[lane * 4 + 2];
        v.w = acc.w * inv + b2[lane * 4 + 3];
    }
    // log_softmax over the 40 values
    float m = fmaxf(fmaxf(v.x, v.y), fmaxf(v.z, v.w));
#pragma unroll
    for (int o = 16; o > 0; o >>= 1) m = fmaxf(m, __shfl_xor_sync(0xffffffff, m, o));
    float sum = 0.0f;
    if (lane < 10)
        sum = __expf(v.x - m) + __expf(v.y - m) + __expf(v.z - m) + __expf(v.w - m);
#pragma unroll
    for (int o = 16; o > 0; o >>= 1) sum += __shfl_xor_sync(0xffffffff, sum, o);
    float l = m + logf(sum);
    if (lane < 10) {
        float4 o4 = make_float4(v.x - l, v.y - l, v.z - l, v.w - l);
        *(float4*)&out[n * OC + lane * 4] = o4;
    }
}

// ---------------- launch -------------------------------------------------------
extern "C" void kernel_launch(void* const* d_in, const int* in_sizes, int n_in,
                              void* d_out, int out_size) {
    const float* x      = (const float*)d_in[0];
    const void*  ei     = d_in[1];
    const float* W1     = (const float*)d_in[2];
    const float* a1_src = (const float*)d_in[3];
    const float* a1_dst = (const float*)d_in[4];
    const float* b1     = (const float*)d_in[5];
    const float* W2     = (const float*)d_in[6];
    const float* a2_src = (const float*)d_in[7];
    const float* a2_dst = (const float*)d_in[8];
    const float* b2     = (const float*)d_in[9];
    float* out = (float*)d_out;

    k_detect<<<1, 1>>>((const unsigned int*)ei);
    k_zero<<<(NN + 255) / 256, 256>>>();
    k_count<<<(EE + 255) / 256, 256>>>(ei);
    k_scan<<<1, 1024>>>();
    k_fill<<<(EE + 255) / 256, 256>>>(ei);
    k_gemm1<<<(NN + 63) / 64, 256>>>(x, W1, a1_src, a1_dst);
    k_node_agg1<<<(NN * 32 + 255) / 256, 256>>>(b1);
    k_gemm2<<<(NN + 127) / 128, 256>>>(W2, a2_src, a2_dst);
    k_node_agg2<<<(NN * 32 + 255) / 256, 256>>>(b2, out);
}

// round 4
// speedup vs baseline: 2.0934x; 1.1715x over previous
#include <cuda_runtime.h>
#include <math.h>

#define NN   50000
#define EE   800000
#define HH   8
#define H1C  128
#define OC   40
#define SLOPE 0.2f
#define NEG_INF __int_as_float(0xff800000)

#define SCAN_B 1024
#define NBLK   ((NN + SCAN_B - 1) / SCAN_B)   // 49

// ---------------- scratch -----------------------------------------------------
__device__ float g_h1[NN * H1C];
__device__ float g_as1[NN * HH];
__device__ float g_ad1[NN * HH];
__device__ float g_agg1[NN * H1C];
__device__ float g_h2[NN * OC];
__device__ float g_as2[NN];
__device__ float g_ad2[NN];
__device__ int   g_deg[NN];
__device__ int   g_off[NN];
__device__ int   g_cur[NN];
__device__ int   g_bsum[NBLK];
__device__ int   g_boff[NBLK];
__device__ int   g_list[EE];           // src ids grouped by dst
__device__ int   g_is64;

// ---------------- helpers -----------------------------------------------------
__device__ __forceinline__ void load_edge(int e, const void* ei, int& s, int& d) {
    if (g_is64) {
        const long long* p = (const long long*)ei;
        s = (int)p[e]; d = (int)p[EE + e];
    } else {
        const int* p = (const int*)ei;
        s = p[e]; d = p[EE + e];
    }
}
__device__ __forceinline__ float leaky(float v) {
    return (v >= 0.0f) ? v : SLOPE * v;
}

// ---------------- CSR build ----------------------------------------------------
__global__ void k_detect(const unsigned int* p) {
    unsigned int acc = 0;
#pragma unroll
    for (int i = 0; i < 16; i++) acc |= p[2 * i + 1];
    g_is64 = (acc == 0) ? 1 : 0;
}

__global__ void k_zero() {
    int i = blockIdx.x * blockDim.x + threadIdx.x;
    if (i < NN) g_deg[i] = 0;
}

__global__ void k_count(const void* __restrict__ ei) {
    int e = blockIdx.x * blockDim.x + threadIdx.x;
    if (e >= EE) return;
    int s, d; load_edge(e, ei, s, d);
    atomicAdd(&g_deg[d], 1);
}

// phase 1: per-block exclusive scan (local), block totals
__global__ void k_scan1() {
    __shared__ int warpsum[32];
    int tid = threadIdx.x;
    int i = blockIdx.x * SCAN_B + tid;
    int v = (i < NN) ? g_deg[i] : 0;
    int x = v;
#pragma unroll
    for (int o = 1; o < 32; o <<= 1) {
        int y = __shfl_up_sync(0xffffffff, x, o);
        if ((tid & 31) >= o) x += y;
    }
    if ((tid & 31) == 31) warpsum[tid >> 5] = x;
    __syncthreads();
    if (tid < 32) {
        int w = warpsum[tid];
#pragma unroll
        for (int o = 1; o < 32; o <<= 1) {
            int y = __shfl_up_sync(0xffffffff, w, o);
            if (tid >= o) w += y;
        }
        warpsum[tid] = w;
    }
    __syncthreads();
    int blockpart = (tid >= 32) ? warpsum[(tid >> 5) - 1] : 0;
    if (i < NN) g_off[i] = blockpart + x - v;          // local exclusive
    if (tid == SCAN_B - 1) g_bsum[blockIdx.x] = blockpart + x;
}

// phase 2: scan the 49 block totals (single warp-ish block)
__global__ void k_scan2() {
    int tid = threadIdx.x;                 // 64 threads
    int v = (tid < NBLK) ? g_bsum[tid] : 0;
    int x = v;
#pragma unroll
    for (int o = 1; o < 32; o <<= 1) {
        int y = __shfl_up_sync(0xffffffff, x, o);
        if ((tid & 31) >= o) x += y;
    }
    __shared__ int w0;
    if (tid == 31) w0 = x;
    __syncthreads();
    int excl = x - v + ((tid >= 32) ? w0 : 0);
    if (tid < NBLK) g_boff[tid] = excl;
}

// phase 3: add block offsets
__global__ void k_scan3() {
    int i = blockIdx.x * blockDim.x + threadIdx.x;
    if (i >= NN) return;
    int o = g_off[i] + g_boff[i / SCAN_B];
    g_off[i] = o;
    g_cur[i] = o;
}

__global__ void k_fill(const void* __restrict__ ei) {
    int e = blockIdx.x * blockDim.x + threadIdx.x;
    if (e >= EE) return;
    int s, d; load_edge(e, ei, s, d);
    int pos = atomicAdd(&g_cur[d], 1);
    g_list[pos] = s;
}

// ---------------- GEMM1: h1 = x @ W1, fused attention halves ------------------
__global__ void k_gemm1(const float* __restrict__ X, const float* __restrict__ W,
                        const float* __restrict__ aS, const float* __restrict__ aD) {
    __shared__ float Xs[64][33];
    __shared__ float Ws[32][128];
    const int tid  = threadIdx.x;              // 256
    const int row0 = blockIdx.x * 64;
    const int lane = tid & 31;
    const int cx   = lane * 4;
    const int ry   = (tid >> 5) * 8;

    float acc[8][4];
#pragma unroll
    for (int i = 0; i < 8; i++)
#pragma unroll
        for (int j = 0; j < 4; j++) acc[i][j] = 0.0f;

    for (int k0 = 0; k0 < 128; k0 += 32) {
#pragma unroll
        for (int i = 0; i < 8; i++) {
            int idx = tid + i * 256;
            int r = idx >> 5, c = idx & 31;
            int gr = row0 + r;
            Xs[r][c] = (gr < NN) ? X[gr * 128 + k0 + c] : 0.0f;
        }
#pragma unroll
        for (int i = 0; i < 16; i++) {
            int idx = tid + i * 256;
            int r = idx >> 7, c = idx & 127;
            Ws[r][c] = W[(k0 + r) * 128 + c];
        }
        __syncthreads();
#pragma unroll
        for (int kk = 0; kk < 32; kk++) {
            float4 wv = *(const float4*)&Ws[kk][cx];
#pragma unroll
            for (int i = 0; i < 8; i++) {
                float xv = Xs[ry + i][kk];
                acc[i][0] += xv * wv.x;
                acc[i][1] += xv * wv.y;
                acc[i][2] += xv * wv.z;
                acc[i][3] += xv * wv.w;
            }
        }
        __syncthreads();
    }

    float as0 = aS[cx], as1 = aS[cx+1], as2 = aS[cx+2], as3 = aS[cx+3];
    float ad0 = aD[cx], ad1 = aD[cx+1], ad2 = aD[cx+2], ad3 = aD[cx+3];

#pragma unroll
    for (int i = 0; i < 8; i++) {
        int gr = row0 + ry + i;
        bool ok = (gr < NN);
        if (ok) {
            float4 v = make_float4(acc[i][0], acc[i][1], acc[i][2], acc[i][3]);
            *(float4*)&g_h1[gr * 128 + cx] = v;
        }
        float ps = acc[i][0]*as0 + acc[i][1]*as1 + acc[i][2]*as2 + acc[i][3]*as3;
        float pd = acc[i][0]*ad0 + acc[i][1]*ad1 + acc[i][2]*ad2 + acc[i][3]*ad3;
        ps += __shfl_xor_sync(0xffffffff, ps, 1);
        ps += __shfl_xor_sync(0xffffffff, ps, 2);
        pd += __shfl_xor_sync(0xffffffff, pd, 1);
        pd += __shfl_xor_sync(0xffffffff, pd, 2);
        if (ok && (lane & 3) == 0) {
            int h = lane >> 2;
            g_as1[gr * HH + h] = ps;
            g_ad1[gr * HH + h] = pd;
        }
    }
}

// ---------------- layer1 aggregation: one warp per node -----------------------
__global__ void k_node_agg1(const float* __restrict__ b1) {
    int gtid = blockIdx.x * blockDim.x + threadIdx.x;
    int n = gtid >> 5;
    if (n >= NN) return;
    int lane = gtid & 31;
    int my_h = lane >> 2;

    float ad = 0.0f, as_self = 0.0f;
    if (lane < 8) {
        ad      = g_ad1[n * 8 + lane];
        as_self = g_as1[n * 8 + lane];
    }
    float ex = (lane < 8) ? __expf(leaky(as_self + ad)) : 0.0f;
    float den = ex;
    float exb = __shfl_sync(0xffffffff, ex, my_h);
    float4 hv = *(const float4*)&g_h1[n * 128 + lane * 4];
    float4 acc = make_float4(exb * hv.x, exb * hv.y, exb * hv.z, exb * hv.w);

    int beg = g_off[n];
    int end = beg + g_deg[n];
    for (int i = beg; i < end; i++) {
        int s = g_list[i];
        float e = 0.0f;
        if (lane < 8) e = __expf(leaky(g_as1[s * 8 + lane] + ad));
        den += e;
        float eb = __shfl_sync(0xffffffff, e, my_h);
        float4 h = *(const float4*)&g_h1[s * 128 + lane * 4];
        acc.x += eb * h.x; acc.y += eb * h.y;
        acc.z += eb * h.z; acc.w += eb * h.w;
    }
    float denb = __shfl_sync(0xffffffff, den, my_h);
    float inv = 1.0f / denb;
    float4 bv = *(const float4*)&b1[lane * 4];
    float4 o;
    o.x = fmaxf(acc.x * inv + bv.x, 0.0f);
    o.y = fmaxf(acc.y * inv + bv.y, 0.0f);
    o.z = fmaxf(acc.z * inv + bv.z, 0.0f);
    o.w = fmaxf(acc.w * inv + bv.w, 0.0f);
    *(float4*)&g_agg1[n * 128 + lane * 4] = o;
}

// ---------------- GEMM2: h2 = agg1 @ W2, fused attention halves ---------------
__global__ void k_gemm2(const float* __restrict__ W,
                        const float* __restrict__ aS, const float* __restrict__ aD) {
    __shared__ float Xs[128][33];
    __shared__ float Ws[32][40];
    const int tid  = threadIdx.x;             // 256
    const int row0 = blockIdx.x * 128;
    const int lane = tid & 31;
    const int cx   = (tid & 7) * 5;
    const int ry   = (tid >> 3) * 4;

    float acc[4][5];
#pragma unroll
    for (int i = 0; i < 4; i++)
#pragma unroll
        for (int j = 0; j < 5; j++) acc[i][j] = 0.0f;

    for (int k0 = 0; k0 < 128; k0 += 32) {
#pragma unroll
        for (int i = 0; i < 16; i++) {
            int idx = tid + i * 256;
            int r = idx >> 5, c = idx & 31;
            int gr = row0 + r;
            Xs[r][c] = (gr < NN) ? g_agg1[gr * 128 + k0 + c] : 0.0f;
        }
#pragma unroll
        for (int i = 0; i < 5; i++) {
            int idx = tid + i * 256;
            int r = idx / 40, c = idx % 40;
            Ws[r][c] = W[(k0 + r) * 40 + c];
        }
        __syncthreads();
#pragma unroll
        for (int kk = 0; kk < 32; kk++) {
            float wv[5];
#pragma unroll
            for (int j = 0; j < 5; j++) wv[j] = Ws[kk][cx + j];
#pragma unroll
            for (int i = 0; i < 4; i++) {
                float xv = Xs[ry + i][kk];
#pragma unroll
                for (int j = 0; j < 5; j++) acc[i][j] += xv * wv[j];
            }
        }
        __syncthreads();
    }

    float asr[5], adr[5];
#pragma unroll
    for (int j = 0; j < 5; j++) { asr[j] = aS[cx + j]; adr[j] = aD[cx + j]; }

#pragma unroll
    for (int i = 0; i < 4; i++) {
        int gr = row0 + ry + i;
        bool ok = (gr < NN);
        if (ok) {
#pragma unroll
            for (int j = 0; j < 5; j++) g_h2[gr * OC + cx + j] = acc[i][j];
        }
        float ps = 0.0f, pd = 0.0f;
#pragma unroll
        for (int j = 0; j < 5; j++) { ps += acc[i][j] * asr[j]; pd += acc[i][j] * adr[j]; }
        ps += __shfl_xor_sync(0xffffffff, ps, 1);
        ps += __shfl_xor_sync(0xffffffff, ps, 2);
        ps += __shfl_xor_sync(0xffffffff, ps, 4);
        pd += __shfl_xor_sync(0xffffffff, pd, 1);
        pd += __shfl_xor_sync(0xffffffff, pd, 2);
        pd += __shfl_xor_sync(0xffffffff, pd, 4);
        if (ok && (lane & 7) == 0) { g_as2[gr] = ps; g_ad2[gr] = pd; }
    }
}

// ---------------- layer2 aggregation + log_softmax ----------------------------
__global__ void k_node_agg2(const float* __restrict__ b2, float* __restrict__ out) {
    int gtid = blockIdx.x * blockDim.x + threadIdx.x;
    int n = gtid >> 5;
    if (n >= NN) return;
    int lane = gtid & 31;

    float ad = g_ad2[n];
    float ex = __expf(leaky(g_as2[n] + ad));
    float den = ex;
    float4 acc = make_float4(0.f, 0.f, 0.f, 0.f);
    if (lane < 10) {
        float4 h = *(const float4*)&g_h2[n * OC + lane * 4];
        acc.x = ex * h.x; acc.y = ex * h.y; acc.z = ex * h.z; acc.w = ex * h.w;
    }

    int beg = g_off[n];
    int end = beg + g_deg[n];
    for (int i = beg; i < end; i++) {
        int s = g_list[i];
        float e = __expf(leaky(g_as2[s] + ad));
        den += e;
        if (lane < 10) {
            float4 h = *(const float4*)&g_h2[s * OC + lane * 4];
            acc.x += e * h.x; acc.y += e * h.y;
            acc.z += e * h.z; acc.w += e * h.w;
        }
    }

    float inv = 1.0f / den;
    float4 v = make_float4(NEG_INF, NEG_INF, NEG_INF, NEG_INF);
    if (lane < 10) {
        v.x = acc.x * inv + b2[lane * 4];
        v.y = acc.y * inv + b2[lane * 4 + 1];
        v.z = acc.z * inv + b2[lane * 4 + 2];
        v.w = acc.w * inv + b2[lane * 4 + 3];
    }
    float m = fmaxf(fmaxf(v.x, v.y), fmaxf(v.z, v.w));
#pragma unroll
    for (int o = 16; o > 0; o >>= 1) m = fmaxf(m, __shfl_xor_sync(0xffffffff, m, o));
    float sum = 0.0f;
    if (lane < 10)
        sum = __expf(v.x - m) + __expf(v.y - m) + __expf(v.z - m) + __expf(v.w - m);
#pragma unroll
    for (int o = 16; o > 0; o >>= 1) sum += __shfl_xor_sync(0xffffffff, sum, o);
    float l = m + logf(sum);
    if (lane < 10) {
        float4 o4 = make_float4(v.x - l, v.y - l, v.z - l, v.w - l);
        *(float4*)&out[n * OC + lane * 4] = o4;
    }
}

// ---------------- launch -------------------------------------------------------
extern "C" void kernel_launch(void* const* d_in, const int* in_sizes, int n_in,
                              void* d_out, int out_size) {
    const float* x      = (const float*)d_in[0];
    const void*  ei     = d_in[1];
    const float* W1     = (const float*)d_in[2];
    const float* a1_src = (const float*)d_in[3];
    const float* a1_dst = (const float*)d_in[4];
    const float* b1     = (const float*)d_in[5];
    const float* W2     = (const float*)d_in[6];
    const float* a2_src = (const float*)d_in[7];
    const float* a2_dst = (const float*)d_in[8];
    const float* b2     = (const float*)d_in[9];
    float* out = (float*)d_out;

    k_detect<<<1, 1>>>((const unsigned int*)ei);
    k_zero<<<(NN + 255) / 256, 256>>>();
    k_count<<<(EE + 255) / 256, 256>>>(ei);
    k_scan1<<<NBLK, SCAN_B>>>();
    k_scan2<<<1, 64>>>();
    k_scan3<<<(NN + 255) / 256, 256>>>();
    k_fill<<<(EE + 255) / 256, 256>>>(ei);
    k_gemm1<<<(NN + 63) / 64, 256>>>(x, W1, a1_src, a1_dst);
    k_node_agg1<<<(NN * 32 + 255) / 256, 256>>>(b1);
    k_gemm2<<<(NN + 127) / 128, 256>>>(W2, a2_src, a2_dst);
    k_node_agg2<<<(NN * 32 + 255) / 256, 256>>>(b2, out);
}